// round 10
// baseline (speedup 1.0000x reference)
#include <cuda_runtime.h>
#include <cstdint>

#define NIMG 256
#define IMGS_PER_BLK 8

// Layers: cin {3,344,352,686,679,1246} cout {344,352,686,679,1246,973}
// conv H=W {32,32,16,16,8,8}, pool after 1,3,5
// WINP {1,12,12,24,24,40}, WOUTP {12,12,24,24,40,32}
// Packed weight words/layer: cum {0,3456,44928,127872,293760,570240}, tot 938880

__device__ uint32_t g_bufA[(size_t)NIMG * 32 * 32 * 12];
__device__ uint32_t g_bufB[(size_t)NIMG * 32 * 32 * 12];
__device__ uint32_t g_wpk[938880];
__device__ int      g_wpw[41472];        // per (layer, wi, tap, cl): popc of weight row
__device__ float2   g_th[4608];          // per-channel (scale, beta - mean*scale)
__device__ uint32_t g_fcpk[10 * 16 * 32];

// Force IMAD (fma pipe) for accumulation; k is a runtime-opaque 1 or 2.
__device__ __forceinline__ void madacc(int& d, int p, int k) {
    asm("mad.lo.s32 %0, %1, %2, %0;" : "+r"(d) : "r"(p), "r"(k));
}

// ---------------------------------------------------------------------------
// Merged pack: x activations + all conv weights (warp ballot).
__global__ void pack_xw_kernel(const float* __restrict__ x,
                               const float* __restrict__ w0, const float* __restrict__ w1,
                               const float* __restrict__ w2, const float* __restrict__ w3,
                               const float* __restrict__ w4, const float* __restrict__ w5,
                               uint32_t* __restrict__ dstx, uint32_t* __restrict__ dstw)
{
    int idx = blockIdx.x * blockDim.x + threadIdx.x;
    if (idx < NIMG * 1024) {
        int n = idx >> 10, pix = idx & 1023;
        const float* xb = x + (size_t)n * 3 * 1024 + pix;
        uint32_t w = 0;
        if (xb[0]    > 0.f) w |= 1u;
        if (xb[1024] > 0.f) w |= 2u;
        if (xb[2048] > 0.f) w |= 4u;
        dstx[idx] = w;
        return;
    }
    const int cum[7]  = {0, 3456, 44928, 127872, 293760, 570240, 938880};
    const int cin[6]  = {3, 344, 352, 686, 679, 1246};
    const int cout[6] = {344, 352, 686, 679, 1246, 973};
    const int winp[6] = {1, 12, 12, 24, 24, 40};

    int warp = (idx >> 5) - 8192;
    int lane = idx & 31;
    if (warp >= 938880) return;

    int l = 0;
#pragma unroll
    for (int i = 1; i < 6; ++i) if (warp >= cum[i]) l = i;

    const float* wsrc = (l == 0) ? w0 : (l == 1) ? w1 : (l == 2) ? w2
                       : (l == 3) ? w3 : (l == 4) ? w4 : w5;
    const int Ci = cin[l], Co = cout[l], WINP = winp[l];

    int widx = warp - cum[l];
    int q   = widx % WINP;  widx /= WINP;
    int cl  = widx & 31;    widx >>= 5;
    int tap = widx % 9;
    int wi  = widx / 9;
    int co  = wi * 32 + cl;
    int ci  = q * 32 + lane;

    float v = 0.f;
    if (co < Co && ci < Ci)
        v = wsrc[((size_t)co * Ci + ci) * 9 + tap];
    uint32_t bits = __ballot_sync(0xFFFFFFFFu, v > 0.f);
    if (lane == 0) dstw[warp] = bits;
}

// ---------------------------------------------------------------------------
// Merged pack: FC weights ballot + per-tap weight popcounts + BN thresholds.
__global__ void pack_misc_kernel(const uint32_t* __restrict__ wpk,
                                 const float* __restrict__ fcw,
                                 const float* __restrict__ p0, const float* __restrict__ p1,
                                 const float* __restrict__ p2, const float* __restrict__ p3,
                                 const float* __restrict__ p4, const float* __restrict__ p5,
                                 int* __restrict__ pw, float2* __restrict__ th,
                                 uint32_t* __restrict__ fcpk)
{
    int idx = blockIdx.x * blockDim.x + threadIdx.x;
    if (idx < 163840) {
        int warp = idx >> 5;
        int lane = idx & 31;
        int wi = warp & 31; int r = warp >> 5;
        int s = r & 15; int o = r >> 4;
        int c = wi * 32 + lane;
        float v = (c < 973) ? fcw[(size_t)o * 15568 + c * 16 + s] : 0.f;
        uint32_t bits = __ballot_sync(0xFFFFFFFFu, v > 0.f);
        if (lane == 0) fcpk[warp] = bits;
    } else if (idx < 163840 + 41472) {
        int i1 = idx - 163840;
        const int cum9[7]  = {0, 3456, 6912, 13824, 20736, 32256, 41472};
        const int woff[6]  = {0, 3456, 44928, 127872, 293760, 570240};
        const int winp[6]  = {1, 12, 12, 24, 24, 40};
        int l = 0;
#pragma unroll
        for (int i = 1; i < 6; ++i) if (i1 >= cum9[i]) l = i;
        int t = i1 - cum9[l];
        int cl  = t & 31;  t >>= 5;
        int tap = t % 9;
        int wi  = t / 9;
        const int WINP = winp[l];
        const uint32_t* src = wpk + woff[l] + (((size_t)wi * 9 + tap) * 32 + cl) * WINP;
        int s = 0;
        for (int q = 0; q < WINP; ++q) s += __popc(src[q]);
        pw[i1] = s;
    } else if (idx < 163840 + 41472 + 4608) {
        int i2 = idx - 163840 - 41472;
        const int cum[7]  = {0, 384, 768, 1536, 2304, 3584, 4608};
        const int cout[6] = {344, 352, 686, 679, 1246, 973};
        int l = 0;
#pragma unroll
        for (int i = 1; i < 6; ++i) if (i2 >= cum[i]) l = i;
        const float* p = (l == 0) ? p0 : (l == 1) ? p1 : (l == 2) ? p2
                        : (l == 3) ? p3 : (l == 4) ? p4 : p5;
        int c = i2 - cum[l];
        int Co = cout[l];
        float2 t;
        if (c < Co) {
            float gg = p[c], bb = p[Co + c], mm = p[2 * Co + c], vv = p[3 * Co + c];
            float sc = gg * rsqrtf(vv + 1e-5f);
            t.x = sc; t.y = bb - mm * sc;
        } else {
            t.x = 0.f; t.y = -1.f;
        }
        th[i2] = t;
    }
}

// ---------------------------------------------------------------------------
// Binary conv 3x3 pad 1, branch-free all-9-taps + edge correction, CSA popc,
// fma-pipe accumulation. Thread = 2 pixels (rows py, py+4 of the same 8x8
// tile) x 4 output channels: weight LDS amortized over 2 pixels, same regs.
// 256 thr = 32 pixel-slots x 8 groups of 4 couts. Output bytes assembled from
// two adjacent lanes' nibbles via shfl_xor(1).
template <int WINP>
__global__ void __launch_bounds__(256, 4)
bconv_kernel(const uint32_t* __restrict__ in, uint8_t* __restrict__ out,
             const uint32_t* __restrict__ wpk, const int* __restrict__ pw,
             const float2* __restrict__ th,
             int H, int W, int Cin, int WOUTP, int tilesX, int one, int two)
{
    extern __shared__ uint32_t sm[];
    uint32_t* sw  = sm;                           // 9*32*WINP
    int*      spw = (int*)(sm + 9 * 32 * WINP);   // 9*32
    uint32_t* sx  = sm + 9 * 32 * WINP + 288;     // 10*10*WINP
    const int tid = threadIdx.x;
    const int wi = blockIdx.y;
    const int x0 = (blockIdx.x % tilesX) * 8;
    const int y0 = (blockIdx.x / tilesX) * 8;

    const uint32_t* wsrc = wpk + (size_t)wi * (9 * 32 * WINP);
    for (int i = tid; i < 9 * 32 * WINP; i += 256) sw[i] = wsrc[i];
    if (tid < 288) spw[tid] = pw[(size_t)wi * 288 + tid];
    { int i2 = tid + 256; if (i2 < 288) spw[i2] = pw[(size_t)wi * 288 + i2]; }

    const int g4 = tid & 7;        // group of 4 couts
    const int ps = tid >> 3;       // pixel slot 0..31
    const int py = ps >> 3;        // row 0..3 (second pixel at py+4)
    const int px = ps & 7;
    const int x  = x0 + px;
    const int yA = y0 + py, yB = y0 + py + 4;

    for (int it = 0; it < IMGS_PER_BLK; ++it) {
        const int n = blockIdx.z * IMGS_PER_BLK + it;
        __syncthreads();
        const uint32_t* ibase = in + (size_t)n * H * W * WINP;
        for (int i = tid; i < 100 * WINP; i += 256) {
            const int w  = i % WINP;
            const int pp = i / WINP;
            const int iy = y0 + pp / 10 - 1;
            const int ix = x0 + pp % 10 - 1;
            uint32_t v = 0u;
            if (iy >= 0 && iy < H && ix >= 0 && ix < W)
                v = ibase[((size_t)iy * W + ix) * WINP + w];
            sx[i] = v;
        }
        __syncthreads();

        int D0[4], D1[4];
#pragma unroll
        for (int j = 0; j < 4; ++j) { D0[j] = 0; D1[j] = 0; }

#pragma unroll 1
        for (int ky = 0; ky < 3; ++ky) {
#pragma unroll 1
            for (int kx = 0; kx < 3; ++kx) {
                const uint32_t* xq0 = &sx[((py + ky) * 10 + (px + kx)) * WINP];
                const uint32_t* xq1 = &sx[((py + 4 + ky) * 10 + (px + kx)) * WINP];
                const uint32_t* wq = &sw[((ky * 3 + kx) * 32 + g4 * 4) * WINP];
                if (WINP == 1) {
                    const uint32_t xv0 = xq0[0];
                    const uint32_t xv1 = xq1[0];
#pragma unroll
                    for (int j = 0; j < 4; ++j) {
                        const uint32_t wv = wq[j];
                        madacc(D0[j], __popc(xv0 ^ wv), one);
                        madacc(D1[j], __popc(xv1 ^ wv), one);
                    }
                } else {
#pragma unroll
                    for (int t3 = 0; t3 < WINP / 12; ++t3) {
                        const uint4 xa0 = *(const uint4*)(xq0 + t3 * 12);
                        const uint4 xa1 = *(const uint4*)(xq0 + t3 * 12 + 4);
                        const uint4 xa2 = *(const uint4*)(xq0 + t3 * 12 + 8);
                        const uint4 xb0 = *(const uint4*)(xq1 + t3 * 12);
                        const uint4 xb1 = *(const uint4*)(xq1 + t3 * 12 + 4);
                        const uint4 xb2 = *(const uint4*)(xq1 + t3 * 12 + 8);
#pragma unroll
                        for (int j = 0; j < 4; ++j) {
                            const uint32_t* wj = wq + j * WINP + t3 * 12;
                            const uint4 w0v = *(const uint4*)(wj);
                            const uint4 w1v = *(const uint4*)(wj + 4);
                            const uint4 w2v = *(const uint4*)(wj + 8);
                            uint32_t a, b, c, s0, s1, s2, s3, m0, m1, m2, m3;
                            // pixel A
                            a = xa0.x ^ w0v.x; b = xa1.x ^ w1v.x; c = xa2.x ^ w2v.x;
                            s0 = a ^ b ^ c; m0 = (a & b) | (c & (a | b));
                            a = xa0.y ^ w0v.y; b = xa1.y ^ w1v.y; c = xa2.y ^ w2v.y;
                            s1 = a ^ b ^ c; m1 = (a & b) | (c & (a | b));
                            a = xa0.z ^ w0v.z; b = xa1.z ^ w1v.z; c = xa2.z ^ w2v.z;
                            s2 = a ^ b ^ c; m2 = (a & b) | (c & (a | b));
                            a = xa0.w ^ w0v.w; b = xa1.w ^ w1v.w; c = xa2.w ^ w2v.w;
                            s3 = a ^ b ^ c; m3 = (a & b) | (c & (a | b));
                            madacc(D0[j], __popc(s0) + __popc(s1) + __popc(s2), one);
                            madacc(D0[j], __popc(s3), one);
                            madacc(D0[j], __popc(m0) + __popc(m1) + __popc(m2), two);
                            madacc(D0[j], __popc(m3), two);
                            // pixel B
                            a = xb0.x ^ w0v.x; b = xb1.x ^ w1v.x; c = xb2.x ^ w2v.x;
                            s0 = a ^ b ^ c; m0 = (a & b) | (c & (a | b));
                            a = xb0.y ^ w0v.y; b = xb1.y ^ w1v.y; c = xb2.y ^ w2v.y;
                            s1 = a ^ b ^ c; m1 = (a & b) | (c & (a | b));
                            a = xb0.z ^ w0v.z; b = xb1.z ^ w1v.z; c = xb2.z ^ w2v.z;
                            s2 = a ^ b ^ c; m2 = (a & b) | (c & (a | b));
                            a = xb0.w ^ w0v.w; b = xb1.w ^ w1v.w; c = xb2.w ^ w2v.w;
                            s3 = a ^ b ^ c; m3 = (a & b) | (c & (a | b));
                            madacc(D1[j], __popc(s0) + __popc(s1) + __popc(s2), one);
                            madacc(D1[j], __popc(s3), one);
                            madacc(D1[j], __popc(m0) + __popc(m1) + __popc(m2), two);
                            madacc(D1[j], __popc(m3), two);
                        }
                    }
                    if (WINP - (WINP / 12) * 12 == 4) {   // WINP=40 leftover uint4
                        const uint4 xv0 = *(const uint4*)(xq0 + (WINP / 12) * 12);
                        const uint4 xv1 = *(const uint4*)(xq1 + (WINP / 12) * 12);
#pragma unroll
                        for (int j = 0; j < 4; ++j) {
                            const uint4 wv = *(const uint4*)(wq + j * WINP + (WINP / 12) * 12);
                            madacc(D0[j], __popc(xv0.x ^ wv.x) + __popc(xv0.y ^ wv.y)
                                        + __popc(xv0.z ^ wv.z), one);
                            madacc(D0[j], __popc(xv0.w ^ wv.w), one);
                            madacc(D1[j], __popc(xv1.x ^ wv.x) + __popc(xv1.y ^ wv.y)
                                        + __popc(xv1.z ^ wv.z), one);
                            madacc(D1[j], __popc(xv1.w ^ wv.w), one);
                        }
                    }
                }
            }
        }

        // Epilogue: two pixels; nibbles merged across adjacent lanes (g4 even/odd).
#pragma unroll
        for (int pp2 = 0; pp2 < 2; ++pp2) {
            const int y = pp2 ? yB : yA;
            const int* Dp = pp2 ? D1 : D0;
            const bool eT = (y == 0), eB = (y == H - 1), eL = (x == 0), eR = (x == W - 1);
            const bool edge = eT | eB | eL | eR;
            const int nvCin = (3 - (int)eT - (int)eB) * (3 - (int)eL - (int)eR) * Cin;
            unsigned nib = 0u;
#pragma unroll
            for (int j = 0; j < 4; ++j) {
                int corr = 0;
                if (edge) {
#pragma unroll
                    for (int ky = 0; ky < 3; ++ky)
#pragma unroll
                        for (int kx = 0; kx < 3; ++kx) {
                            const bool inv = (eT && ky == 0) || (eB && ky == 2)
                                          || (eL && kx == 0) || (eR && kx == 2);
                            if (inv) corr += spw[(ky * 3 + kx) * 32 + g4 * 4 + j];
                        }
                }
                const int idot = nvCin - 2 * Dp[j] + 2 * corr;
                const float2 t = __ldg(&th[wi * 32 + g4 * 4 + j]);
                if (fmaf((float)idot, t.x, t.y) > 0.0f) nib |= 1u << j;
            }
            const unsigned other = __shfl_xor_sync(0xFFFFFFFFu, nib, 1);
            if (!(g4 & 1)) {
                out[(((size_t)n * H * W + (size_t)y * W + x) * WOUTP + wi) * 4 + (g4 >> 1)]
                    = (uint8_t)(nib | (other << 4));
            }
        }
    }
}

// Maxpool 2x2 on packed bits == bitwise OR (BN scale > 0, monotone)
__global__ void pool_kernel(const uint32_t* __restrict__ in, uint32_t* __restrict__ out,
                            int Ho, int Wo, int WORDS, int total)
{
    int idx = blockIdx.x * blockDim.x + threadIdx.x;
    if (idx >= total) return;
    int w = idx % WORDS; int r = idx / WORDS;
    int xo = r % Wo; r /= Wo;
    int yo = r % Ho; int n = r / Ho;
    const int Wi = Wo * 2;
    size_t base = (((size_t)n * (Ho * 2) + yo * 2) * Wi + xo * 2) * WORDS + w;
    size_t rs = (size_t)Wi * WORDS;
    out[idx] = in[base] | in[base + WORDS] | in[base + rs] | in[base + rs + WORDS];
}

// Binary FC: out[n][o] = 15568 - 2*popc(x ^ w) + fcb[o]
__global__ void fc_kernel(const uint32_t* __restrict__ xb, const uint32_t* __restrict__ wb,
                          const float* __restrict__ fcb, float* __restrict__ out)
{
    int t = blockIdx.x * blockDim.x + threadIdx.x;
    if (t >= NIMG * 10) return;
    int n = t / 10, o = t - n * 10;
    const uint4* xa = (const uint4*)(xb + (size_t)n * 512);
    const uint4* wa = (const uint4*)(wb + (size_t)o * 512);
    int D = 0;
#pragma unroll 8
    for (int i = 0; i < 128; ++i) {
        uint4 a = xa[i], b = wa[i];
        D += __popc(a.x ^ b.x) + __popc(a.y ^ b.y) + __popc(a.z ^ b.z) + __popc(a.w ^ b.w);
    }
    out[t] = (float)(15568 - 2 * D) + fcb[o];
}

// ---------------------------------------------------------------------------
extern "C" void kernel_launch(void* const* d_in, const int* in_sizes, int n_in,
                              void* d_out, int out_size)
{
    static const int s_cin[6]   = {3, 344, 352, 686, 679, 1246};
    static const int s_H[6]     = {32, 32, 16, 16, 8, 8};
    static const int s_winp[6]  = {1, 12, 12, 24, 24, 40};
    static const int s_woutp[6] = {12, 12, 24, 24, 40, 32};
    static const size_t s_woff[6] = {0, 3456, 44928, 127872, 293760, 570240};
    static const size_t s_toff[6] = {0, 384, 768, 1536, 2304, 3584};

    const long long szw[6] = {344LL*3*9, 352LL*344*9, 686LL*352*9,
                              679LL*686*9, 1246LL*679*9, 973LL*1246*9};
    const long long szp[6] = {4LL*344, 4LL*352, 4LL*686, 4LL*679, 4LL*1246, 4LL*973};
    auto find = [&](long long s) -> const void* {
        for (int i = 0; i < n_in; ++i)
            if ((long long)in_sizes[i] == s) return d_in[i];
        return (const void*)0;
    };
    const float* x   = (const float*)find(256LL * 3 * 32 * 32);
    const float* fcw = (const float*)find(10LL * 15568);
    const float* fcb = (const float*)find(10);
    const float* w[6]; const float* p[6];
    for (int i = 0; i < 6; ++i) {
        w[i] = (const float*)find(szw[i]);
        p[i] = (const float*)find(szp[i]);
    }
    if (!x || !fcw || !fcb) return;

    void *pA, *pB, *pW, *pPW, *pT, *pF;
    cudaGetSymbolAddress(&pA, g_bufA);
    cudaGetSymbolAddress(&pB, g_bufB);
    cudaGetSymbolAddress(&pW, g_wpk);
    cudaGetSymbolAddress(&pPW, g_wpw);
    cudaGetSymbolAddress(&pT, g_th);
    cudaGetSymbolAddress(&pF, g_fcpk);
    uint32_t* bufA = (uint32_t*)pA;
    uint32_t* bufB = (uint32_t*)pB;
    uint32_t* wpk  = (uint32_t*)pW;
    int*      wpw  = (int*)pPW;
    float2*   th   = (float2*)pT;
    uint32_t* fcpk = (uint32_t*)pF;

    auto smemFor = [](int winp) { return (size_t)(9 * 32 * winp + 288 + 100 * winp) * 4; };
    cudaFuncSetAttribute(bconv_kernel<40>, cudaFuncAttributeMaxDynamicSharedMemorySize, (int)smemFor(40));
    cudaFuncSetAttribute(bconv_kernel<24>, cudaFuncAttributeMaxDynamicSharedMemorySize, (int)smemFor(24));

    // --- pack phase: 2 launches ---
    {
        int tot = NIMG * 1024 + 938880 * 32;
        pack_xw_kernel<<<(tot + 255) / 256, 256>>>(x, w[0], w[1], w[2], w[3], w[4], w[5],
                                                   bufA, wpk);
    }
    {
        int tot = 163840 + 41472 + 4608;
        pack_misc_kernel<<<(tot + 255) / 256, 256>>>(wpk, fcw, p[0], p[1], p[2], p[3], p[4], p[5],
                                                     wpw, th, fcpk);
    }

    // --- conv stack ---
    auto conv = [&](int l, const uint32_t* src, uint32_t* dst) {
        int H = s_H[l], W = H;
        int WINP = s_winp[l], WOUTP = s_woutp[l], Cin = s_cin[l];
        int tilesX = W / 8;
        dim3 grid((unsigned)((H / 8) * tilesX), (unsigned)WOUTP,
                  (unsigned)(NIMG / IMGS_PER_BLK));
        size_t smem = smemFor(WINP);
        uint8_t* ob = (uint8_t*)dst;
        const uint32_t* wb = wpk + s_woff[l];
        const int* pwb = wpw + s_toff[l] * 9;
        const float2* tb = th + s_toff[l];
        switch (WINP) {
            case 1:  bconv_kernel<1><<<grid, 256, smem>>>(src, ob, wb, pwb, tb, H, W, Cin, WOUTP, tilesX, 1, 2); break;
            case 12: bconv_kernel<12><<<grid, 256, smem>>>(src, ob, wb, pwb, tb, H, W, Cin, WOUTP, tilesX, 1, 2); break;
            case 24: bconv_kernel<24><<<grid, 256, smem>>>(src, ob, wb, pwb, tb, H, W, Cin, WOUTP, tilesX, 1, 2); break;
            case 40: bconv_kernel<40><<<grid, 256, smem>>>(src, ob, wb, pwb, tb, H, W, Cin, WOUTP, tilesX, 1, 2); break;
        }
    };

    conv(0, bufA, bufB);                                    // B: [32,32,12]
    conv(1, bufB, bufA);                                    // A: conv-space [32,32,12]
    {   int tot = NIMG * 16 * 16 * 12;
        pool_kernel<<<(tot + 255) / 256, 256>>>(bufA, bufB, 16, 16, 12, tot); }  // B: [16,16,12]
    conv(2, bufB, bufA);                                    // A: [16,16,24]
    conv(3, bufA, bufB);                                    // B: conv-space [16,16,24]
    {   int tot = NIMG * 8 * 8 * 24;
        pool_kernel<<<(tot + 255) / 256, 256>>>(bufB, bufA, 8, 8, 24, tot); }    // A: [8,8,24]
    conv(4, bufA, bufB);                                    // B: [8,8,40]
    conv(5, bufB, bufA);                                    // A: conv-space [8,8,32]
    {   int tot = NIMG * 4 * 4 * 32;
        pool_kernel<<<(tot + 255) / 256, 256>>>(bufA, bufB, 4, 4, 32, tot); }    // B: [4,4,32]

    // --- FC ---
    fc_kernel<<<10, 256>>>(bufB, fcpk, fcb, (float*)d_out);
}

// round 11
// speedup vs baseline: 1.9105x; 1.9105x over previous
#include <cuda_runtime.h>
#include <cstdint>

#define NIMG 256
#define IMGS_PER_BLK 8

// Layers: cin {3,344,352,686,679,1246} cout {344,352,686,679,1246,973}
// conv H=W {32,32,16,16,8,8}, pool after 1,3,5
// WINP {1,12,12,24,24,40}, WOUTP {12,12,24,24,40,32}
// Packed weight words/layer: cum {0,3456,44928,127872,293760,570240}, tot 938880

__device__ uint32_t g_bufA[(size_t)NIMG * 32 * 32 * 12];
__device__ uint32_t g_bufB[(size_t)NIMG * 32 * 32 * 12];
__device__ uint32_t g_wpk[938880];
__device__ int      g_wpw[41472];        // per (layer, wi, tap, cl): popc of weight row
__device__ float2   g_th[4608];          // per-channel (scale, beta - mean*scale)
__device__ uint32_t g_fcpk[10 * 16 * 32];

// Force IMAD (fma pipe) for accumulation; k is a runtime-opaque 1 or 2.
__device__ __forceinline__ void madacc(int& d, int p, int k) {
    asm("mad.lo.s32 %0, %1, %2, %0;" : "+r"(d) : "r"(p), "r"(k));
}

// ---------------------------------------------------------------------------
// Merged pack: x activations + all conv weights (warp ballot).
__global__ void pack_xw_kernel(const float* __restrict__ x,
                               const float* __restrict__ w0, const float* __restrict__ w1,
                               const float* __restrict__ w2, const float* __restrict__ w3,
                               const float* __restrict__ w4, const float* __restrict__ w5,
                               uint32_t* __restrict__ dstx, uint32_t* __restrict__ dstw)
{
    int idx = blockIdx.x * blockDim.x + threadIdx.x;
    if (idx < NIMG * 1024) {
        int n = idx >> 10, pix = idx & 1023;
        const float* xb = x + (size_t)n * 3 * 1024 + pix;
        uint32_t w = 0;
        if (xb[0]    > 0.f) w |= 1u;
        if (xb[1024] > 0.f) w |= 2u;
        if (xb[2048] > 0.f) w |= 4u;
        dstx[idx] = w;
        return;
    }
    const int cum[7]  = {0, 3456, 44928, 127872, 293760, 570240, 938880};
    const int cin[6]  = {3, 344, 352, 686, 679, 1246};
    const int cout[6] = {344, 352, 686, 679, 1246, 973};
    const int winp[6] = {1, 12, 12, 24, 24, 40};

    int warp = (idx >> 5) - 8192;
    int lane = idx & 31;
    if (warp >= 938880) return;

    int l = 0;
#pragma unroll
    for (int i = 1; i < 6; ++i) if (warp >= cum[i]) l = i;

    const float* wsrc = (l == 0) ? w0 : (l == 1) ? w1 : (l == 2) ? w2
                       : (l == 3) ? w3 : (l == 4) ? w4 : w5;
    const int Ci = cin[l], Co = cout[l], WINP = winp[l];

    int widx = warp - cum[l];
    int q   = widx % WINP;  widx /= WINP;
    int cl  = widx & 31;    widx >>= 5;
    int tap = widx % 9;
    int wi  = widx / 9;
    int co  = wi * 32 + cl;
    int ci  = q * 32 + lane;

    float v = 0.f;
    if (co < Co && ci < Ci)
        v = wsrc[((size_t)co * Ci + ci) * 9 + tap];
    uint32_t bits = __ballot_sync(0xFFFFFFFFu, v > 0.f);
    if (lane == 0) dstw[warp] = bits;
}

// ---------------------------------------------------------------------------
// Merged pack: FC weights ballot + per-tap weight popcounts + BN thresholds.
__global__ void pack_misc_kernel(const uint32_t* __restrict__ wpk,
                                 const float* __restrict__ fcw,
                                 const float* __restrict__ p0, const float* __restrict__ p1,
                                 const float* __restrict__ p2, const float* __restrict__ p3,
                                 const float* __restrict__ p4, const float* __restrict__ p5,
                                 int* __restrict__ pw, float2* __restrict__ th,
                                 uint32_t* __restrict__ fcpk)
{
    int idx = blockIdx.x * blockDim.x + threadIdx.x;
    if (idx < 163840) {
        int warp = idx >> 5;
        int lane = idx & 31;
        int wi = warp & 31; int r = warp >> 5;
        int s = r & 15; int o = r >> 4;
        int c = wi * 32 + lane;
        float v = (c < 973) ? fcw[(size_t)o * 15568 + c * 16 + s] : 0.f;
        uint32_t bits = __ballot_sync(0xFFFFFFFFu, v > 0.f);
        if (lane == 0) fcpk[warp] = bits;
    } else if (idx < 163840 + 41472) {
        int i1 = idx - 163840;
        const int cum9[7]  = {0, 3456, 6912, 13824, 20736, 32256, 41472};
        const int woff[6]  = {0, 3456, 44928, 127872, 293760, 570240};
        const int winp[6]  = {1, 12, 12, 24, 24, 40};
        int l = 0;
#pragma unroll
        for (int i = 1; i < 6; ++i) if (i1 >= cum9[i]) l = i;
        int t = i1 - cum9[l];
        int cl  = t & 31;  t >>= 5;
        int tap = t % 9;
        int wi  = t / 9;
        const int WINP = winp[l];
        const uint32_t* src = wpk + woff[l] + (((size_t)wi * 9 + tap) * 32 + cl) * WINP;
        int s = 0;
        for (int q = 0; q < WINP; ++q) s += __popc(src[q]);
        pw[i1] = s;
    } else if (idx < 163840 + 41472 + 4608) {
        int i2 = idx - 163840 - 41472;
        const int cum[7]  = {0, 384, 768, 1536, 2304, 3584, 4608};
        const int cout[6] = {344, 352, 686, 679, 1246, 973};
        int l = 0;
#pragma unroll
        for (int i = 1; i < 6; ++i) if (i2 >= cum[i]) l = i;
        const float* p = (l == 0) ? p0 : (l == 1) ? p1 : (l == 2) ? p2
                        : (l == 3) ? p3 : (l == 4) ? p4 : p5;
        int c = i2 - cum[l];
        int Co = cout[l];
        float2 t;
        if (c < Co) {
            float gg = p[c], bb = p[Co + c], mm = p[2 * Co + c], vv = p[3 * Co + c];
            float sc = gg * rsqrtf(vv + 1e-5f);
            t.x = sc; t.y = bb - mm * sc;
        } else {
            t.x = 0.f; t.y = -1.f;
        }
        th[i2] = t;
    }
}

// ---------------------------------------------------------------------------
// Binary conv 3x3 pad 1, branch-free all-9-taps + edge correction, CSA popc,
// fma-pipe accumulation. 128 threads = 4 warps; warp w = cout-group g of 8
// couts (weight LDS warp-uniform -> broadcast); lane = pixel slot (py 0..3,
// px 0..7); each thread computes rows py and py+4 of the 8x8 tile, so each
// weight uint4 load feeds TWO pixels (LDS per pixel-tap: 27 -> 15).
template <int WINP>
__global__ void __launch_bounds__(128, 6)
bconv_kernel(const uint32_t* __restrict__ in, uint8_t* __restrict__ out,
             const uint32_t* __restrict__ wpk, const int* __restrict__ pw,
             const float2* __restrict__ th,
             int H, int W, int Cin, int WOUTP, int tilesX, int one, int two)
{
    extern __shared__ uint32_t sm[];
    uint32_t* sw  = sm;                           // 9*32*WINP
    int*      spw = (int*)(sm + 9 * 32 * WINP);   // 9*32
    uint32_t* sx  = sm + 9 * 32 * WINP + 288;     // 10*10*WINP
    const int tid = threadIdx.x;
    const int wi = blockIdx.y;
    const int x0 = (blockIdx.x % tilesX) * 8;
    const int y0 = (blockIdx.x / tilesX) * 8;

    const uint32_t* wsrc = wpk + (size_t)wi * (9 * 32 * WINP);
    for (int i = tid; i < 9 * 32 * WINP; i += 128) sw[i] = wsrc[i];
    for (int i = tid; i < 288; i += 128) spw[i] = pw[(size_t)wi * 288 + i];

    const int g  = tid >> 5;       // cout group (warp-uniform)
    const int sl = tid & 31;       // pixel slot
    const int py = sl >> 3;        // row 0..3 (second pixel at py+4)
    const int px = sl & 7;
    const int x  = x0 + px;
    const int yA = y0 + py, yB = y0 + py + 4;

    for (int it = 0; it < IMGS_PER_BLK; ++it) {
        const int n = blockIdx.z * IMGS_PER_BLK + it;
        __syncthreads();
        const uint32_t* ibase = in + (size_t)n * H * W * WINP;
        for (int i = tid; i < 100 * WINP; i += 128) {
            const int w  = i % WINP;
            const int pp = i / WINP;
            const int iy = y0 + pp / 10 - 1;
            const int ix = x0 + pp % 10 - 1;
            uint32_t v = 0u;
            if (iy >= 0 && iy < H && ix >= 0 && ix < W)
                v = ibase[((size_t)iy * W + ix) * WINP + w];
            sx[i] = v;
        }
        __syncthreads();

        int D0[8], D1[8];
#pragma unroll
        for (int j = 0; j < 8; ++j) { D0[j] = 0; D1[j] = 0; }

#pragma unroll 1
        for (int ky = 0; ky < 3; ++ky) {
#pragma unroll 1
            for (int kx = 0; kx < 3; ++kx) {
                const uint32_t* xq0 = &sx[((py + ky) * 10 + (px + kx)) * WINP];
                const uint32_t* xq1 = &sx[((py + 4 + ky) * 10 + (px + kx)) * WINP];
                const uint32_t* wq = &sw[((ky * 3 + kx) * 32 + g * 8) * WINP];
                if (WINP == 1) {
                    const uint32_t xv0 = xq0[0];
                    const uint32_t xv1 = xq1[0];
#pragma unroll
                    for (int j = 0; j < 8; ++j) {
                        const uint32_t wv = wq[j];
                        madacc(D0[j], __popc(xv0 ^ wv), one);
                        madacc(D1[j], __popc(xv1 ^ wv), one);
                    }
                } else {
#pragma unroll
                    for (int t3 = 0; t3 < WINP / 12; ++t3) {
                        const uint4 xa0 = *(const uint4*)(xq0 + t3 * 12);
                        const uint4 xa1 = *(const uint4*)(xq0 + t3 * 12 + 4);
                        const uint4 xa2 = *(const uint4*)(xq0 + t3 * 12 + 8);
                        const uint4 xb0 = *(const uint4*)(xq1 + t3 * 12);
                        const uint4 xb1 = *(const uint4*)(xq1 + t3 * 12 + 4);
                        const uint4 xb2 = *(const uint4*)(xq1 + t3 * 12 + 8);
#pragma unroll
                        for (int j = 0; j < 8; ++j) {
                            const uint32_t* wj = wq + j * WINP + t3 * 12;
                            const uint4 w0v = *(const uint4*)(wj);
                            const uint4 w1v = *(const uint4*)(wj + 4);
                            const uint4 w2v = *(const uint4*)(wj + 8);
                            uint32_t a, b, c, s0, s1, s2, s3, m0, m1, m2, m3;
                            // pixel A
                            a = xa0.x ^ w0v.x; b = xa1.x ^ w1v.x; c = xa2.x ^ w2v.x;
                            s0 = a ^ b ^ c; m0 = (a & b) | (c & (a | b));
                            a = xa0.y ^ w0v.y; b = xa1.y ^ w1v.y; c = xa2.y ^ w2v.y;
                            s1 = a ^ b ^ c; m1 = (a & b) | (c & (a | b));
                            a = xa0.z ^ w0v.z; b = xa1.z ^ w1v.z; c = xa2.z ^ w2v.z;
                            s2 = a ^ b ^ c; m2 = (a & b) | (c & (a | b));
                            a = xa0.w ^ w0v.w; b = xa1.w ^ w1v.w; c = xa2.w ^ w2v.w;
                            s3 = a ^ b ^ c; m3 = (a & b) | (c & (a | b));
                            madacc(D0[j], __popc(s0) + __popc(s1) + __popc(s2), one);
                            madacc(D0[j], __popc(s3), one);
                            madacc(D0[j], __popc(m0) + __popc(m1) + __popc(m2), two);
                            madacc(D0[j], __popc(m3), two);
                            // pixel B
                            a = xb0.x ^ w0v.x; b = xb1.x ^ w1v.x; c = xb2.x ^ w2v.x;
                            s0 = a ^ b ^ c; m0 = (a & b) | (c & (a | b));
                            a = xb0.y ^ w0v.y; b = xb1.y ^ w1v.y; c = xb2.y ^ w2v.y;
                            s1 = a ^ b ^ c; m1 = (a & b) | (c & (a | b));
                            a = xb0.z ^ w0v.z; b = xb1.z ^ w1v.z; c = xb2.z ^ w2v.z;
                            s2 = a ^ b ^ c; m2 = (a & b) | (c & (a | b));
                            a = xb0.w ^ w0v.w; b = xb1.w ^ w1v.w; c = xb2.w ^ w2v.w;
                            s3 = a ^ b ^ c; m3 = (a & b) | (c & (a | b));
                            madacc(D1[j], __popc(s0) + __popc(s1) + __popc(s2), one);
                            madacc(D1[j], __popc(s3), one);
                            madacc(D1[j], __popc(m0) + __popc(m1) + __popc(m2), two);
                            madacc(D1[j], __popc(m3), two);
                        }
                    }
                    if (WINP - (WINP / 12) * 12 == 4) {   // WINP=40 leftover uint4
                        const uint4 xv0 = *(const uint4*)(xq0 + (WINP / 12) * 12);
                        const uint4 xv1 = *(const uint4*)(xq1 + (WINP / 12) * 12);
#pragma unroll
                        for (int j = 0; j < 8; ++j) {
                            const uint4 wv = *(const uint4*)(wq + j * WINP + (WINP / 12) * 12);
                            madacc(D0[j], __popc(xv0.x ^ wv.x) + __popc(xv0.y ^ wv.y)
                                        + __popc(xv0.z ^ wv.z), one);
                            madacc(D0[j], __popc(xv0.w ^ wv.w), one);
                            madacc(D1[j], __popc(xv1.x ^ wv.x) + __popc(xv1.y ^ wv.y)
                                        + __popc(xv1.z ^ wv.z), one);
                            madacc(D1[j], __popc(xv1.w ^ wv.w), one);
                        }
                    }
                }
            }
        }

        // Epilogue: both pixels, one byte each (same as round-8 format).
#pragma unroll
        for (int pp2 = 0; pp2 < 2; ++pp2) {
            const int y = pp2 ? yB : yA;
            const int* Dp = pp2 ? D1 : D0;
            const bool eT = (y == 0), eB = (y == H - 1), eL = (x == 0), eR = (x == W - 1);
            const bool edge = eT | eB | eL | eR;
            const int nvCin = (3 - (int)eT - (int)eB) * (3 - (int)eL - (int)eR) * Cin;
            unsigned bytev = 0u;
#pragma unroll
            for (int j = 0; j < 8; ++j) {
                int corr = 0;
                if (edge) {
#pragma unroll
                    for (int ky = 0; ky < 3; ++ky)
#pragma unroll
                        for (int kx = 0; kx < 3; ++kx) {
                            const bool inv = (eT && ky == 0) || (eB && ky == 2)
                                          || (eL && kx == 0) || (eR && kx == 2);
                            if (inv) corr += spw[(ky * 3 + kx) * 32 + g * 8 + j];
                        }
                }
                const int idot = nvCin - 2 * Dp[j] + 2 * corr;
                const float2 t = __ldg(&th[wi * 32 + g * 8 + j]);
                if (fmaf((float)idot, t.x, t.y) > 0.0f) bytev |= 1u << j;
            }
            out[(((size_t)n * H * W + (size_t)y * W + x) * WOUTP + wi) * 4 + g]
                = (uint8_t)bytev;
        }
    }
}

// Maxpool 2x2 on packed bits == bitwise OR (BN scale > 0, monotone)
__global__ void pool_kernel(const uint32_t* __restrict__ in, uint32_t* __restrict__ out,
                            int Ho, int Wo, int WORDS, int total)
{
    int idx = blockIdx.x * blockDim.x + threadIdx.x;
    if (idx >= total) return;
    int w = idx % WORDS; int r = idx / WORDS;
    int xo = r % Wo; r /= Wo;
    int yo = r % Ho; int n = r / Ho;
    const int Wi = Wo * 2;
    size_t base = (((size_t)n * (Ho * 2) + yo * 2) * Wi + xo * 2) * WORDS + w;
    size_t rs = (size_t)Wi * WORDS;
    out[idx] = in[base] | in[base + WORDS] | in[base + rs] | in[base + rs + WORDS];
}

// Binary FC: out[n][o] = 15568 - 2*popc(x ^ w) + fcb[o]
__global__ void fc_kernel(const uint32_t* __restrict__ xb, const uint32_t* __restrict__ wb,
                          const float* __restrict__ fcb, float* __restrict__ out)
{
    int t = blockIdx.x * blockDim.x + threadIdx.x;
    if (t >= NIMG * 10) return;
    int n = t / 10, o = t - n * 10;
    const uint4* xa = (const uint4*)(xb + (size_t)n * 512);
    const uint4* wa = (const uint4*)(wb + (size_t)o * 512);
    int D = 0;
#pragma unroll 8
    for (int i = 0; i < 128; ++i) {
        uint4 a = xa[i], b = wa[i];
        D += __popc(a.x ^ b.x) + __popc(a.y ^ b.y) + __popc(a.z ^ b.z) + __popc(a.w ^ b.w);
    }
    out[t] = (float)(15568 - 2 * D) + fcb[o];
}

// ---------------------------------------------------------------------------
extern "C" void kernel_launch(void* const* d_in, const int* in_sizes, int n_in,
                              void* d_out, int out_size)
{
    static const int s_cin[6]   = {3, 344, 352, 686, 679, 1246};
    static const int s_H[6]     = {32, 32, 16, 16, 8, 8};
    static const int s_winp[6]  = {1, 12, 12, 24, 24, 40};
    static const int s_woutp[6] = {12, 12, 24, 24, 40, 32};
    static const size_t s_woff[6] = {0, 3456, 44928, 127872, 293760, 570240};
    static const size_t s_toff[6] = {0, 384, 768, 1536, 2304, 3584};

    const long long szw[6] = {344LL*3*9, 352LL*344*9, 686LL*352*9,
                              679LL*686*9, 1246LL*679*9, 973LL*1246*9};
    const long long szp[6] = {4LL*344, 4LL*352, 4LL*686, 4LL*679, 4LL*1246, 4LL*973};
    auto find = [&](long long s) -> const void* {
        for (int i = 0; i < n_in; ++i)
            if ((long long)in_sizes[i] == s) return d_in[i];
        return (const void*)0;
    };
    const float* x   = (const float*)find(256LL * 3 * 32 * 32);
    const float* fcw = (const float*)find(10LL * 15568);
    const float* fcb = (const float*)find(10);
    const float* w[6]; const float* p[6];
    for (int i = 0; i < 6; ++i) {
        w[i] = (const float*)find(szw[i]);
        p[i] = (const float*)find(szp[i]);
    }
    if (!x || !fcw || !fcb) return;

    void *pA, *pB, *pW, *pPW, *pT, *pF;
    cudaGetSymbolAddress(&pA, g_bufA);
    cudaGetSymbolAddress(&pB, g_bufB);
    cudaGetSymbolAddress(&pW, g_wpk);
    cudaGetSymbolAddress(&pPW, g_wpw);
    cudaGetSymbolAddress(&pT, g_th);
    cudaGetSymbolAddress(&pF, g_fcpk);
    uint32_t* bufA = (uint32_t*)pA;
    uint32_t* bufB = (uint32_t*)pB;
    uint32_t* wpk  = (uint32_t*)pW;
    int*      wpw  = (int*)pPW;
    float2*   th   = (float2*)pT;
    uint32_t* fcpk = (uint32_t*)pF;

    auto smemFor = [](int winp) { return (size_t)(9 * 32 * winp + 288 + 100 * winp) * 4; };
    cudaFuncSetAttribute(bconv_kernel<40>, cudaFuncAttributeMaxDynamicSharedMemorySize, (int)smemFor(40));
    cudaFuncSetAttribute(bconv_kernel<24>, cudaFuncAttributeMaxDynamicSharedMemorySize, (int)smemFor(24));

    // --- pack phase: 2 launches ---
    {
        int tot = NIMG * 1024 + 938880 * 32;
        pack_xw_kernel<<<(tot + 255) / 256, 256>>>(x, w[0], w[1], w[2], w[3], w[4], w[5],
                                                   bufA, wpk);
    }
    {
        int tot = 163840 + 41472 + 4608;
        pack_misc_kernel<<<(tot + 255) / 256, 256>>>(wpk, fcw, p[0], p[1], p[2], p[3], p[4], p[5],
                                                     wpw, th, fcpk);
    }

    // --- conv stack ---
    auto conv = [&](int l, const uint32_t* src, uint32_t* dst) {
        int H = s_H[l], W = H;
        int WINP = s_winp[l], WOUTP = s_woutp[l], Cin = s_cin[l];
        int tilesX = W / 8;
        dim3 grid((unsigned)((H / 8) * tilesX), (unsigned)WOUTP,
                  (unsigned)(NIMG / IMGS_PER_BLK));
        size_t smem = smemFor(WINP);
        uint8_t* ob = (uint8_t*)dst;
        const uint32_t* wb = wpk + s_woff[l];
        const int* pwb = wpw + s_toff[l] * 9;
        const float2* tb = th + s_toff[l];
        switch (WINP) {
            case 1:  bconv_kernel<1><<<grid, 128, smem>>>(src, ob, wb, pwb, tb, H, W, Cin, WOUTP, tilesX, 1, 2); break;
            case 12: bconv_kernel<12><<<grid, 128, smem>>>(src, ob, wb, pwb, tb, H, W, Cin, WOUTP, tilesX, 1, 2); break;
            case 24: bconv_kernel<24><<<grid, 128, smem>>>(src, ob, wb, pwb, tb, H, W, Cin, WOUTP, tilesX, 1, 2); break;
            case 40: bconv_kernel<40><<<grid, 128, smem>>>(src, ob, wb, pwb, tb, H, W, Cin, WOUTP, tilesX, 1, 2); break;
        }
    };

    conv(0, bufA, bufB);                                    // B: [32,32,12]
    conv(1, bufB, bufA);                                    // A: conv-space [32,32,12]
    {   int tot = NIMG * 16 * 16 * 12;
        pool_kernel<<<(tot + 255) / 256, 256>>>(bufA, bufB, 16, 16, 12, tot); }  // B: [16,16,12]
    conv(2, bufB, bufA);                                    // A: [16,16,24]
    conv(3, bufA, bufB);                                    // B: conv-space [16,16,24]
    {   int tot = NIMG * 8 * 8 * 24;
        pool_kernel<<<(tot + 255) / 256, 256>>>(bufB, bufA, 8, 8, 24, tot); }    // A: [8,8,24]
    conv(4, bufA, bufB);                                    // B: [8,8,40]
    conv(5, bufB, bufA);                                    // A: conv-space [8,8,32]
    {   int tot = NIMG * 4 * 4 * 32;
        pool_kernel<<<(tot + 255) / 256, 256>>>(bufA, bufB, 4, 4, 32, tot); }    // B: [4,4,32]

    // --- FC ---
    fc_kernel<<<10, 256>>>(bufB, fcpk, fcb, (float*)d_out);
}

// round 12
// speedup vs baseline: 2.2312x; 1.1679x over previous
#include <cuda_runtime.h>
#include <cstdint>

#define NIMG 256
#define IMGS_PER_BLK 8

// Layers: cin {3,344,352,686,679,1246} cout {344,352,686,679,1246,973}
// conv H=W {32,32,16,16,8,8}, pool after 1,3,5
// WINP {1,12,12,24,24,40}, WOUTP {12,12,24,24,40,32}
// Packed weight words/layer: cum {0,3456,44928,127872,293760,570240}, tot 938880

__device__ uint32_t g_bufA[(size_t)NIMG * 32 * 32 * 12];
__device__ uint32_t g_bufB[(size_t)NIMG * 32 * 32 * 12];
__device__ uint32_t g_wpk[938880];
__device__ int      g_wpw[41472];        // per (layer, wi, tap, cl): popc of weight row
__device__ float2   g_th[4608];          // per-channel (scale, beta - mean*scale)
__device__ uint32_t g_fcpk[10 * 16 * 32];

// Force IMAD (fma pipe) for accumulation; k is a runtime-opaque 1 or 2.
__device__ __forceinline__ void madacc(int& d, int p, int k) {
    asm("mad.lo.s32 %0, %1, %2, %0;" : "+r"(d) : "r"(p), "r"(k));
}

// ---------------------------------------------------------------------------
// Merged pack: x activations + all conv weights.
// Weight part: one warp per (layer, wi, cl, q); lane = ci within the 32-ch word;
// each thread reads 9 CONTIGUOUS floats (all taps) -> 9 ballots. Coalesced-ish:
// 9x less wasted traffic than the old one-float-per-thread gather.
// Warp counts per layer WOUTP*32*WINP: {384,4608,9216,18432,30720,40960}.
__global__ void pack_xw_kernel(const float* __restrict__ x,
                               const float* __restrict__ w0, const float* __restrict__ w1,
                               const float* __restrict__ w2, const float* __restrict__ w3,
                               const float* __restrict__ w4, const float* __restrict__ w5,
                               uint32_t* __restrict__ dstx, uint32_t* __restrict__ dstw)
{
    int idx = blockIdx.x * blockDim.x + threadIdx.x;
    if (idx < NIMG * 1024) {
        int n = idx >> 10, pix = idx & 1023;
        const float* xb = x + (size_t)n * 3 * 1024 + pix;
        uint32_t w = 0;
        if (xb[0]    > 0.f) w |= 1u;
        if (xb[1024] > 0.f) w |= 2u;
        if (xb[2048] > 0.f) w |= 4u;
        dstx[idx] = w;
        return;
    }
    const int cumw[7] = {0, 384, 4992, 14208, 32640, 63360, 104320};
    const int woff[6] = {0, 3456, 44928, 127872, 293760, 570240};
    const int cin[6]  = {3, 344, 352, 686, 679, 1246};
    const int cout[6] = {344, 352, 686, 679, 1246, 973};
    const int winp[6] = {1, 12, 12, 24, 24, 40};

    int wn = (idx >> 5) - 8192;
    int lane = idx & 31;
    if (wn >= 104320) return;

    int l = 0;
#pragma unroll
    for (int i = 1; i < 6; ++i) if (wn >= cumw[i]) l = i;

    const float* wsrc = (l == 0) ? w0 : (l == 1) ? w1 : (l == 2) ? w2
                       : (l == 3) ? w3 : (l == 4) ? w4 : w5;
    const int Ci = cin[l], Co = cout[l], WINP = winp[l];

    int widx = wn - cumw[l];
    int q  = widx % WINP;  widx /= WINP;
    int cl = widx & 31;
    int wi = widx >> 5;
    int co = wi * 32 + cl;
    int ci = q * 32 + lane;

    const bool valid = (co < Co && ci < Ci);
    const float* src = valid ? (wsrc + ((size_t)co * Ci + ci) * 9) : wsrc;
    uint32_t* dbase = dstw + woff[l] + ((size_t)wi * 9 * 32 + cl) * WINP + q;
#pragma unroll
    for (int tap = 0; tap < 9; ++tap) {
        float v = valid ? src[tap] : 0.f;
        uint32_t bits = __ballot_sync(0xFFFFFFFFu, valid && v > 0.f);
        if (lane == 0) dbase[(size_t)tap * 32 * WINP] = bits;
    }
}

// ---------------------------------------------------------------------------
// Merged pack: FC weights ballot + per-tap weight popcounts + BN thresholds.
__global__ void pack_misc_kernel(const uint32_t* __restrict__ wpk,
                                 const float* __restrict__ fcw,
                                 const float* __restrict__ p0, const float* __restrict__ p1,
                                 const float* __restrict__ p2, const float* __restrict__ p3,
                                 const float* __restrict__ p4, const float* __restrict__ p5,
                                 int* __restrict__ pw, float2* __restrict__ th,
                                 uint32_t* __restrict__ fcpk)
{
    int idx = blockIdx.x * blockDim.x + threadIdx.x;
    if (idx < 163840) {
        int warp = idx >> 5;
        int lane = idx & 31;
        int wi = warp & 31; int r = warp >> 5;
        int s = r & 15; int o = r >> 4;
        int c = wi * 32 + lane;
        float v = (c < 973) ? fcw[(size_t)o * 15568 + c * 16 + s] : 0.f;
        uint32_t bits = __ballot_sync(0xFFFFFFFFu, v > 0.f);
        if (lane == 0) fcpk[warp] = bits;
    } else if (idx < 163840 + 41472) {
        int i1 = idx - 163840;
        const int cum9[7]  = {0, 3456, 6912, 13824, 20736, 32256, 41472};
        const int woff[6]  = {0, 3456, 44928, 127872, 293760, 570240};
        const int winp[6]  = {1, 12, 12, 24, 24, 40};
        int l = 0;
#pragma unroll
        for (int i = 1; i < 6; ++i) if (i1 >= cum9[i]) l = i;
        int t = i1 - cum9[l];
        int cl  = t & 31;  t >>= 5;
        int tap = t % 9;
        int wi  = t / 9;
        const int WINP = winp[l];
        const uint32_t* src = wpk + woff[l] + (((size_t)wi * 9 + tap) * 32 + cl) * WINP;
        int s = 0;
        for (int q = 0; q < WINP; ++q) s += __popc(src[q]);
        pw[i1] = s;
    } else if (idx < 163840 + 41472 + 4608) {
        int i2 = idx - 163840 - 41472;
        const int cum[7]  = {0, 384, 768, 1536, 2304, 3584, 4608};
        const int cout[6] = {344, 352, 686, 679, 1246, 973};
        int l = 0;
#pragma unroll
        for (int i = 1; i < 6; ++i) if (i2 >= cum[i]) l = i;
        const float* p = (l == 0) ? p0 : (l == 1) ? p1 : (l == 2) ? p2
                        : (l == 3) ? p3 : (l == 4) ? p4 : p5;
        int c = i2 - cum[l];
        int Co = cout[l];
        float2 t;
        if (c < Co) {
            float gg = p[c], bb = p[Co + c], mm = p[2 * Co + c], vv = p[3 * Co + c];
            float sc = gg * rsqrtf(vv + 1e-5f);
            t.x = sc; t.y = bb - mm * sc;
        } else {
            t.x = 0.f; t.y = -1.f;
        }
        th[i2] = t;
    }
}

// ---------------------------------------------------------------------------
// Binary conv 3x3 pad 1, branch-free all-9-taps + edge correction, CSA popc,
// fma-pipe accumulation. Round-8 layout: 256 thr = 64 pixels x 4 groups of 8
// couts, 8 images per block. kx loop fully unrolled (3-tap scheduling window).
template <int WINP>
__global__ void __launch_bounds__(256, 4)
bconv_kernel(const uint32_t* __restrict__ in, uint8_t* __restrict__ out,
             const uint32_t* __restrict__ wpk, const int* __restrict__ pw,
             const float2* __restrict__ th,
             int H, int W, int Cin, int WOUTP, int tilesX, int one, int two)
{
    extern __shared__ uint32_t sm[];
    uint32_t* sw  = sm;                           // 9*32*WINP
    int*      spw = (int*)(sm + 9 * 32 * WINP);   // 9*32
    uint32_t* sx  = sm + 9 * 32 * WINP + 288;     // 10*10*WINP
    const int tid = threadIdx.x;
    const int wi = blockIdx.y;
    const int x0 = (blockIdx.x % tilesX) * 8;
    const int y0 = (blockIdx.x / tilesX) * 8;

    const uint32_t* wsrc = wpk + (size_t)wi * (9 * 32 * WINP);
    for (int i = tid; i < 9 * 32 * WINP; i += 256) sw[i] = wsrc[i];
    if (tid < 288) spw[tid] = pw[(size_t)wi * 288 + tid];
    { int i2 = tid + 256; if (i2 < 288) spw[i2] = pw[(size_t)wi * 288 + i2]; }

    const int g  = tid >> 6;
    const int p  = tid & 63;
    const int py = p >> 3;
    const int px = p & 7;

    for (int it = 0; it < IMGS_PER_BLK; ++it) {
        const int n = blockIdx.z * IMGS_PER_BLK + it;
        __syncthreads();
        const uint32_t* ibase = in + (size_t)n * H * W * WINP;
        for (int i = tid; i < 100 * WINP; i += 256) {
            const int w  = i % WINP;
            const int pp = i / WINP;
            const int iy = y0 + pp / 10 - 1;
            const int ix = x0 + pp % 10 - 1;
            uint32_t v = 0u;
            if (iy >= 0 && iy < H && ix >= 0 && ix < W)
                v = ibase[((size_t)iy * W + ix) * WINP + w];
            sx[i] = v;
        }
        __syncthreads();

        int D[8];
#pragma unroll
        for (int j = 0; j < 8; ++j) D[j] = 0;

#pragma unroll 1
        for (int ky = 0; ky < 3; ++ky) {
            const uint32_t* xrow = &sx[((py + ky) * 10 + px) * WINP];
            const uint32_t* wrow = &sw[(ky * 3 * 32 + g * 8) * WINP];
#pragma unroll
            for (int kx = 0; kx < 3; ++kx) {
                const uint32_t* xp = xrow + kx * WINP;
                const uint32_t* wp = wrow + kx * 32 * WINP;
                if (WINP == 1) {
                    const uint32_t xv = xp[0];
#pragma unroll
                    for (int j = 0; j < 8; ++j)
                        madacc(D[j], __popc(xv ^ wp[j]), one);
                } else {
#pragma unroll
                    for (int t3 = 0; t3 < WINP / 12; ++t3) {
                        const uint4 x0v = *(const uint4*)(xp + t3 * 12);
                        const uint4 x1v = *(const uint4*)(xp + t3 * 12 + 4);
                        const uint4 x2v = *(const uint4*)(xp + t3 * 12 + 8);
#pragma unroll
                        for (int j = 0; j < 8; ++j) {
                            const uint32_t* wj = wp + j * WINP + t3 * 12;
                            const uint4 w0v = *(const uint4*)(wj);
                            const uint4 w1v = *(const uint4*)(wj + 4);
                            const uint4 w2v = *(const uint4*)(wj + 8);
                            uint32_t a, b, c;
                            uint32_t s0, s1, s2, s3, m0, m1, m2, m3;
                            a = x0v.x ^ w0v.x; b = x1v.x ^ w1v.x; c = x2v.x ^ w2v.x;
                            s0 = a ^ b ^ c; m0 = (a & b) | (c & (a | b));
                            a = x0v.y ^ w0v.y; b = x1v.y ^ w1v.y; c = x2v.y ^ w2v.y;
                            s1 = a ^ b ^ c; m1 = (a & b) | (c & (a | b));
                            a = x0v.z ^ w0v.z; b = x1v.z ^ w1v.z; c = x2v.z ^ w2v.z;
                            s2 = a ^ b ^ c; m2 = (a & b) | (c & (a | b));
                            a = x0v.w ^ w0v.w; b = x1v.w ^ w1v.w; c = x2v.w ^ w2v.w;
                            s3 = a ^ b ^ c; m3 = (a & b) | (c & (a | b));
                            madacc(D[j], __popc(s0) + __popc(s1) + __popc(s2), one);
                            madacc(D[j], __popc(s3), one);
                            madacc(D[j], __popc(m0) + __popc(m1) + __popc(m2), two);
                            madacc(D[j], __popc(m3), two);
                        }
                    }
                    if (WINP - (WINP / 12) * 12 == 4) {   // WINP=40 leftover uint4
                        const uint4 xv = *(const uint4*)(xp + (WINP / 12) * 12);
#pragma unroll
                        for (int j = 0; j < 8; ++j) {
                            const uint4 wv = *(const uint4*)(wp + j * WINP + (WINP / 12) * 12);
                            madacc(D[j], __popc(xv.x ^ wv.x) + __popc(xv.y ^ wv.y)
                                       + __popc(xv.z ^ wv.z), one);
                            madacc(D[j], __popc(xv.w ^ wv.w), one);
                        }
                    }
                }
            }
        }

        const int y = y0 + py, x = x0 + px;
        const bool eT = (y == 0), eB = (y == H - 1), eL = (x == 0), eR = (x == W - 1);
        const bool edge = eT | eB | eL | eR;
        const int nvCin = (3 - (int)eT - (int)eB) * (3 - (int)eL - (int)eR) * Cin;
        unsigned bytev = 0u;
#pragma unroll
        for (int j = 0; j < 8; ++j) {
            int corr = 0;
            if (edge) {
#pragma unroll
                for (int ky = 0; ky < 3; ++ky)
#pragma unroll
                    for (int kx = 0; kx < 3; ++kx) {
                        const bool inv = (eT && ky == 0) || (eB && ky == 2)
                                      || (eL && kx == 0) || (eR && kx == 2);
                        if (inv) corr += spw[(ky * 3 + kx) * 32 + g * 8 + j];
                    }
            }
            const int idot = nvCin - 2 * D[j] + 2 * corr;
            const float2 t = __ldg(&th[wi * 32 + g * 8 + j]);
            if (fmaf((float)idot, t.x, t.y) > 0.0f) bytev |= 1u << j;
        }
        out[(((size_t)n * H * W + (size_t)y * W + x) * WOUTP + wi) * 4 + g]
            = (uint8_t)bytev;
    }
}

// Maxpool 2x2 on packed bits == bitwise OR (BN scale > 0, monotone)
__global__ void pool_kernel(const uint32_t* __restrict__ in, uint32_t* __restrict__ out,
                            int Ho, int Wo, int WORDS, int total)
{
    int idx = blockIdx.x * blockDim.x + threadIdx.x;
    if (idx >= total) return;
    int w = idx % WORDS; int r = idx / WORDS;
    int xo = r % Wo; r /= Wo;
    int yo = r % Ho; int n = r / Ho;
    const int Wi = Wo * 2;
    size_t base = (((size_t)n * (Ho * 2) + yo * 2) * Wi + xo * 2) * WORDS + w;
    size_t rs = (size_t)Wi * WORDS;
    out[idx] = in[base] | in[base + WORDS] | in[base + rs] | in[base + rs + WORDS];
}

// Binary FC: out[n][o] = 15568 - 2*popc(x ^ w) + fcb[o]
__global__ void fc_kernel(const uint32_t* __restrict__ xb, const uint32_t* __restrict__ wb,
                          const float* __restrict__ fcb, float* __restrict__ out)
{
    int t = blockIdx.x * blockDim.x + threadIdx.x;
    if (t >= NIMG * 10) return;
    int n = t / 10, o = t - n * 10;
    const uint4* xa = (const uint4*)(xb + (size_t)n * 512);
    const uint4* wa = (const uint4*)(wb + (size_t)o * 512);
    int D = 0;
#pragma unroll 8
    for (int i = 0; i < 128; ++i) {
        uint4 a = xa[i], b = wa[i];
        D += __popc(a.x ^ b.x) + __popc(a.y ^ b.y) + __popc(a.z ^ b.z) + __popc(a.w ^ b.w);
    }
    out[t] = (float)(15568 - 2 * D) + fcb[o];
}

// ---------------------------------------------------------------------------
extern "C" void kernel_launch(void* const* d_in, const int* in_sizes, int n_in,
                              void* d_out, int out_size)
{
    static const int s_cin[6]   = {3, 344, 352, 686, 679, 1246};
    static const int s_H[6]     = {32, 32, 16, 16, 8, 8};
    static const int s_winp[6]  = {1, 12, 12, 24, 24, 40};
    static const int s_woutp[6] = {12, 12, 24, 24, 40, 32};
    static const size_t s_woff[6] = {0, 3456, 44928, 127872, 293760, 570240};
    static const size_t s_toff[6] = {0, 384, 768, 1536, 2304, 3584};

    const long long szw[6] = {344LL*3*9, 352LL*344*9, 686LL*352*9,
                              679LL*686*9, 1246LL*679*9, 973LL*1246*9};
    const long long szp[6] = {4LL*344, 4LL*352, 4LL*686, 4LL*679, 4LL*1246, 4LL*973};
    auto find = [&](long long s) -> const void* {
        for (int i = 0; i < n_in; ++i)
            if ((long long)in_sizes[i] == s) return d_in[i];
        return (const void*)0;
    };
    const float* x   = (const float*)find(256LL * 3 * 32 * 32);
    const float* fcw = (const float*)find(10LL * 15568);
    const float* fcb = (const float*)find(10);
    const float* w[6]; const float* p[6];
    for (int i = 0; i < 6; ++i) {
        w[i] = (const float*)find(szw[i]);
        p[i] = (const float*)find(szp[i]);
    }
    if (!x || !fcw || !fcb) return;

    void *pA, *pB, *pW, *pPW, *pT, *pF;
    cudaGetSymbolAddress(&pA, g_bufA);
    cudaGetSymbolAddress(&pB, g_bufB);
    cudaGetSymbolAddress(&pW, g_wpk);
    cudaGetSymbolAddress(&pPW, g_wpw);
    cudaGetSymbolAddress(&pT, g_th);
    cudaGetSymbolAddress(&pF, g_fcpk);
    uint32_t* bufA = (uint32_t*)pA;
    uint32_t* bufB = (uint32_t*)pB;
    uint32_t* wpk  = (uint32_t*)pW;
    int*      wpw  = (int*)pPW;
    float2*   th   = (float2*)pT;
    uint32_t* fcpk = (uint32_t*)pF;

    auto smemFor = [](int winp) { return (size_t)(9 * 32 * winp + 288 + 100 * winp) * 4; };
    cudaFuncSetAttribute(bconv_kernel<40>, cudaFuncAttributeMaxDynamicSharedMemorySize, (int)smemFor(40));
    cudaFuncSetAttribute(bconv_kernel<24>, cudaFuncAttributeMaxDynamicSharedMemorySize, (int)smemFor(24));

    // --- pack phase: 2 launches ---
    {
        int tot = NIMG * 1024 + 104320 * 32;
        pack_xw_kernel<<<(tot + 255) / 256, 256>>>(x, w[0], w[1], w[2], w[3], w[4], w[5],
                                                   bufA, wpk);
    }
    {
        int tot = 163840 + 41472 + 4608;
        pack_misc_kernel<<<(tot + 255) / 256, 256>>>(wpk, fcw, p[0], p[1], p[2], p[3], p[4], p[5],
                                                     wpw, th, fcpk);
    }

    // --- conv stack ---
    auto conv = [&](int l, const uint32_t* src, uint32_t* dst) {
        int H = s_H[l], W = H;
        int WINP = s_winp[l], WOUTP = s_woutp[l], Cin = s_cin[l];
        int tilesX = W / 8;
        dim3 grid((unsigned)((H / 8) * tilesX), (unsigned)WOUTP,
                  (unsigned)(NIMG / IMGS_PER_BLK));
        size_t smem = smemFor(WINP);
        uint8_t* ob = (uint8_t*)dst;
        const uint32_t* wb = wpk + s_woff[l];
        const int* pwb = wpw + s_toff[l] * 9;
        const float2* tb = th + s_toff[l];
        switch (WINP) {
            case 1:  bconv_kernel<1><<<grid, 256, smem>>>(src, ob, wb, pwb, tb, H, W, Cin, WOUTP, tilesX, 1, 2); break;
            case 12: bconv_kernel<12><<<grid, 256, smem>>>(src, ob, wb, pwb, tb, H, W, Cin, WOUTP, tilesX, 1, 2); break;
            case 24: bconv_kernel<24><<<grid, 256, smem>>>(src, ob, wb, pwb, tb, H, W, Cin, WOUTP, tilesX, 1, 2); break;
            case 40: bconv_kernel<40><<<grid, 256, smem>>>(src, ob, wb, pwb, tb, H, W, Cin, WOUTP, tilesX, 1, 2); break;
        }
    };

    conv(0, bufA, bufB);                                    // B: [32,32,12]
    conv(1, bufB, bufA);                                    // A: conv-space [32,32,12]
    {   int tot = NIMG * 16 * 16 * 12;
        pool_kernel<<<(tot + 255) / 256, 256>>>(bufA, bufB, 16, 16, 12, tot); }  // B: [16,16,12]
    conv(2, bufB, bufA);                                    // A: [16,16,24]
    conv(3, bufA, bufB);                                    // B: conv-space [16,16,24]
    {   int tot = NIMG * 8 * 8 * 24;
        pool_kernel<<<(tot + 255) / 256, 256>>>(bufB, bufA, 8, 8, 24, tot); }    // A: [8,8,24]
    conv(4, bufA, bufB);                                    // B: [8,8,40]
    conv(5, bufB, bufA);                                    // A: conv-space [8,8,32]
    {   int tot = NIMG * 4 * 4 * 32;
        pool_kernel<<<(tot + 255) / 256, 256>>>(bufA, bufB, 4, 4, 32, tot); }    // B: [4,4,32]

    // --- FC ---
    fc_kernel<<<10, 256>>>(bufB, fcpk, fcb, (float*)d_out);
}

// round 13
// speedup vs baseline: 2.4073x; 1.0789x over previous
#include <cuda_runtime.h>
#include <cstdint>

#define NIMG 256
#define IMGS_PER_BLK 8

// Layers: cin {3,344,352,686,679,1246} cout {344,352,686,679,1246,973}
// conv H=W {32,32,16,16,8,8}, pool after 1,3,5
// WINP (storage stride) {1,12,12,24,24,40}, WOUTP stride {12,12,24,24,40,32}
// grid.y (computed cout groups) {12,11,24,22,40,31}: pad groups of l1/l3/l5
// are zero-filled by the following pool instead of being computed.
// Packed weight words/layer: cum {0,3456,44928,127872,293760,570240}, tot 938880

__device__ uint32_t g_bufA[(size_t)NIMG * 32 * 32 * 12];
__device__ uint32_t g_bufB[(size_t)NIMG * 32 * 32 * 12];
__device__ uint32_t g_wpk[938880];
__device__ int      g_wpw[41472];        // per (layer, wi, tap, cl): popc of weight row
__device__ float2   g_th[4608];          // per-channel (scale, beta - mean*scale)
__device__ uint32_t g_fcpk[10 * 16 * 32];

// Force IMAD (fma pipe) for accumulation; k is a runtime-opaque 1 or 2.
__device__ __forceinline__ void madacc(int& d, int p, int k) {
    asm("mad.lo.s32 %0, %1, %2, %0;" : "+r"(d) : "r"(p), "r"(k));
}

// ---------------------------------------------------------------------------
// Merged pack: x activations + all conv weights.
// Weight part: one warp per (layer, wi, cl, q); each thread reads 9 contiguous
// floats (all taps) -> 9 ballots.
__global__ void pack_xw_kernel(const float* __restrict__ x,
                               const float* __restrict__ w0, const float* __restrict__ w1,
                               const float* __restrict__ w2, const float* __restrict__ w3,
                               const float* __restrict__ w4, const float* __restrict__ w5,
                               uint32_t* __restrict__ dstx, uint32_t* __restrict__ dstw)
{
    int idx = blockIdx.x * blockDim.x + threadIdx.x;
    if (idx < NIMG * 1024) {
        int n = idx >> 10, pix = idx & 1023;
        const float* xb = x + (size_t)n * 3 * 1024 + pix;
        uint32_t w = 0;
        if (xb[0]    > 0.f) w |= 1u;
        if (xb[1024] > 0.f) w |= 2u;
        if (xb[2048] > 0.f) w |= 4u;
        dstx[idx] = w;
        return;
    }
    const int cumw[7] = {0, 384, 4992, 14208, 32640, 63360, 104320};
    const int woff[6] = {0, 3456, 44928, 127872, 293760, 570240};
    const int cin[6]  = {3, 344, 352, 686, 679, 1246};
    const int cout[6] = {344, 352, 686, 679, 1246, 973};
    const int winp[6] = {1, 12, 12, 24, 24, 40};

    int wn = (idx >> 5) - 8192;
    int lane = idx & 31;
    if (wn >= 104320) return;

    int l = 0;
#pragma unroll
    for (int i = 1; i < 6; ++i) if (wn >= cumw[i]) l = i;

    const float* wsrc = (l == 0) ? w0 : (l == 1) ? w1 : (l == 2) ? w2
                       : (l == 3) ? w3 : (l == 4) ? w4 : w5;
    const int Ci = cin[l], Co = cout[l], WINP = winp[l];

    int widx = wn - cumw[l];
    int q  = widx % WINP;  widx /= WINP;
    int cl = widx & 31;
    int wi = widx >> 5;
    int co = wi * 32 + cl;
    int ci = q * 32 + lane;

    const bool valid = (co < Co && ci < Ci);
    const float* src = valid ? (wsrc + ((size_t)co * Ci + ci) * 9) : wsrc;
    uint32_t* dbase = dstw + woff[l] + ((size_t)wi * 9 * 32 + cl) * WINP + q;
#pragma unroll
    for (int tap = 0; tap < 9; ++tap) {
        float v = valid ? src[tap] : 0.f;
        uint32_t bits = __ballot_sync(0xFFFFFFFFu, valid && v > 0.f);
        if (lane == 0) dbase[(size_t)tap * 32 * WINP] = bits;
    }
}

// ---------------------------------------------------------------------------
// Merged pack: FC weights ballot + per-tap weight popcounts + BN thresholds.
__global__ void pack_misc_kernel(const uint32_t* __restrict__ wpk,
                                 const float* __restrict__ fcw,
                                 const float* __restrict__ p0, const float* __restrict__ p1,
                                 const float* __restrict__ p2, const float* __restrict__ p3,
                                 const float* __restrict__ p4, const float* __restrict__ p5,
                                 int* __restrict__ pw, float2* __restrict__ th,
                                 uint32_t* __restrict__ fcpk)
{
    int idx = blockIdx.x * blockDim.x + threadIdx.x;
    if (idx < 163840) {
        int warp = idx >> 5;
        int lane = idx & 31;
        int wi = warp & 31; int r = warp >> 5;
        int s = r & 15; int o = r >> 4;
        int c = wi * 32 + lane;
        float v = (c < 973) ? fcw[(size_t)o * 15568 + c * 16 + s] : 0.f;
        uint32_t bits = __ballot_sync(0xFFFFFFFFu, v > 0.f);
        if (lane == 0) fcpk[warp] = bits;
    } else if (idx < 163840 + 41472) {
        int i1 = idx - 163840;
        const int cum9[7]  = {0, 3456, 6912, 13824, 20736, 32256, 41472};
        const int woff[6]  = {0, 3456, 44928, 127872, 293760, 570240};
        const int winp[6]  = {1, 12, 12, 24, 24, 40};
        int l = 0;
#pragma unroll
        for (int i = 1; i < 6; ++i) if (i1 >= cum9[i]) l = i;
        int t = i1 - cum9[l];
        int cl  = t & 31;  t >>= 5;
        int tap = t % 9;
        int wi  = t / 9;
        const int WINP = winp[l];
        const uint32_t* src = wpk + woff[l] + (((size_t)wi * 9 + tap) * 32 + cl) * WINP;
        int s = 0;
        for (int q = 0; q < WINP; ++q) s += __popc(src[q]);
        pw[i1] = s;
    } else if (idx < 163840 + 41472 + 4608) {
        int i2 = idx - 163840 - 41472;
        const int cum[7]  = {0, 384, 768, 1536, 2304, 3584, 4608};
        const int cout[6] = {344, 352, 686, 679, 1246, 973};
        int l = 0;
#pragma unroll
        for (int i = 1; i < 6; ++i) if (i2 >= cum[i]) l = i;
        const float* p = (l == 0) ? p0 : (l == 1) ? p1 : (l == 2) ? p2
                        : (l == 3) ? p3 : (l == 4) ? p4 : p5;
        int c = i2 - cum[l];
        int Co = cout[l];
        float2 t;
        if (c < Co) {
            float gg = p[c], bb = p[Co + c], mm = p[2 * Co + c], vv = p[3 * Co + c];
            float sc = gg * rsqrtf(vv + 1e-5f);
            t.x = sc; t.y = bb - mm * sc;
        } else {
            t.x = 0.f; t.y = -1.f;
        }
        th[i2] = t;
    }
}

// ---------------------------------------------------------------------------
// Binary conv 3x3 pad 1, branch-free all-9-taps + edge correction, CSA popc.
// ALL popcount accumulation via mad.lo.s32 (fma pipe) — zero IADD3 on the alu
// pipe in the hot loop. 256 thr = 64 pixels x 4 groups of 8 couts; kx unrolled.
template <int WINP>
__global__ void __launch_bounds__(256, 4)
bconv_kernel(const uint32_t* __restrict__ in, uint8_t* __restrict__ out,
             const uint32_t* __restrict__ wpk, const int* __restrict__ pw,
             const float2* __restrict__ th,
             int H, int W, int Cin, int WOUTP, int tilesX, int one, int two)
{
    extern __shared__ uint32_t sm[];
    uint32_t* sw  = sm;                           // 9*32*WINP
    int*      spw = (int*)(sm + 9 * 32 * WINP);   // 9*32
    uint32_t* sx  = sm + 9 * 32 * WINP + 288;     // 10*10*WINP
    const int tid = threadIdx.x;
    const int wi = blockIdx.y;
    const int x0 = (blockIdx.x % tilesX) * 8;
    const int y0 = (blockIdx.x / tilesX) * 8;

    const uint32_t* wsrc = wpk + (size_t)wi * (9 * 32 * WINP);
    for (int i = tid; i < 9 * 32 * WINP; i += 256) sw[i] = wsrc[i];
    if (tid < 288) spw[tid] = pw[(size_t)wi * 288 + tid];
    { int i2 = tid + 256; if (i2 < 288) spw[i2] = pw[(size_t)wi * 288 + i2]; }

    const int g  = tid >> 6;
    const int p  = tid & 63;
    const int py = p >> 3;
    const int px = p & 7;

    for (int it = 0; it < IMGS_PER_BLK; ++it) {
        const int n = blockIdx.z * IMGS_PER_BLK + it;
        __syncthreads();
        const uint32_t* ibase = in + (size_t)n * H * W * WINP;
        for (int i = tid; i < 100 * WINP; i += 256) {
            const int w  = i % WINP;
            const int pp = i / WINP;
            const int iy = y0 + pp / 10 - 1;
            const int ix = x0 + pp % 10 - 1;
            uint32_t v = 0u;
            if (iy >= 0 && iy < H && ix >= 0 && ix < W)
                v = ibase[((size_t)iy * W + ix) * WINP + w];
            sx[i] = v;
        }
        __syncthreads();

        int D[8];
#pragma unroll
        for (int j = 0; j < 8; ++j) D[j] = 0;

#pragma unroll 1
        for (int ky = 0; ky < 3; ++ky) {
            const uint32_t* xrow = &sx[((py + ky) * 10 + px) * WINP];
            const uint32_t* wrow = &sw[(ky * 3 * 32 + g * 8) * WINP];
#pragma unroll
            for (int kx = 0; kx < 3; ++kx) {
                const uint32_t* xp = xrow + kx * WINP;
                const uint32_t* wp = wrow + kx * 32 * WINP;
                if (WINP == 1) {
                    const uint32_t xv = xp[0];
#pragma unroll
                    for (int j = 0; j < 8; ++j)
                        madacc(D[j], __popc(xv ^ wp[j]), one);
                } else {
#pragma unroll
                    for (int t3 = 0; t3 < WINP / 12; ++t3) {
                        const uint4 x0v = *(const uint4*)(xp + t3 * 12);
                        const uint4 x1v = *(const uint4*)(xp + t3 * 12 + 4);
                        const uint4 x2v = *(const uint4*)(xp + t3 * 12 + 8);
#pragma unroll
                        for (int j = 0; j < 8; ++j) {
                            const uint32_t* wj = wp + j * WINP + t3 * 12;
                            const uint4 w0v = *(const uint4*)(wj);
                            const uint4 w1v = *(const uint4*)(wj + 4);
                            const uint4 w2v = *(const uint4*)(wj + 8);
                            uint32_t a, b, c;
                            uint32_t s0, s1, s2, s3, m0, m1, m2, m3;
                            a = x0v.x ^ w0v.x; b = x1v.x ^ w1v.x; c = x2v.x ^ w2v.x;
                            s0 = a ^ b ^ c; m0 = (a & b) | (c & (a | b));
                            a = x0v.y ^ w0v.y; b = x1v.y ^ w1v.y; c = x2v.y ^ w2v.y;
                            s1 = a ^ b ^ c; m1 = (a & b) | (c & (a | b));
                            a = x0v.z ^ w0v.z; b = x1v.z ^ w1v.z; c = x2v.z ^ w2v.z;
                            s2 = a ^ b ^ c; m2 = (a & b) | (c & (a | b));
                            a = x0v.w ^ w0v.w; b = x1v.w ^ w1v.w; c = x2v.w ^ w2v.w;
                            s3 = a ^ b ^ c; m3 = (a & b) | (c & (a | b));
                            madacc(D[j], __popc(s0), one);
                            madacc(D[j], __popc(s1), one);
                            madacc(D[j], __popc(s2), one);
                            madacc(D[j], __popc(s3), one);
                            madacc(D[j], __popc(m0), two);
                            madacc(D[j], __popc(m1), two);
                            madacc(D[j], __popc(m2), two);
                            madacc(D[j], __popc(m3), two);
                        }
                    }
                    if (WINP - (WINP / 12) * 12 == 4) {   // WINP=40 leftover uint4
                        const uint4 xv = *(const uint4*)(xp + (WINP / 12) * 12);
#pragma unroll
                        for (int j = 0; j < 8; ++j) {
                            const uint4 wv = *(const uint4*)(wp + j * WINP + (WINP / 12) * 12);
                            madacc(D[j], __popc(xv.x ^ wv.x), one);
                            madacc(D[j], __popc(xv.y ^ wv.y), one);
                            madacc(D[j], __popc(xv.z ^ wv.z), one);
                            madacc(D[j], __popc(xv.w ^ wv.w), one);
                        }
                    }
                }
            }
        }

        const int y = y0 + py, x = x0 + px;
        const bool eT = (y == 0), eB = (y == H - 1), eL = (x == 0), eR = (x == W - 1);
        const bool edge = eT | eB | eL | eR;
        const int nvCin = (3 - (int)eT - (int)eB) * (3 - (int)eL - (int)eR) * Cin;
        unsigned bytev = 0u;
#pragma unroll
        for (int j = 0; j < 8; ++j) {
            int corr = 0;
            if (edge) {
#pragma unroll
                for (int ky = 0; ky < 3; ++ky)
#pragma unroll
                    for (int kx = 0; kx < 3; ++kx) {
                        const bool inv = (eT && ky == 0) || (eB && ky == 2)
                                      || (eL && kx == 0) || (eR && kx == 2);
                        if (inv) corr += spw[(ky * 3 + kx) * 32 + g * 8 + j];
                    }
            }
            const int idot = nvCin - 2 * D[j] + 2 * corr;
            const float2 t = __ldg(&th[wi * 32 + g * 8 + j]);
            if (fmaf((float)idot, t.x, t.y) > 0.0f) bytev |= 1u << j;
        }
        out[(((size_t)n * H * W + (size_t)y * W + x) * WOUTP + wi) * 4 + g]
            = (uint8_t)bytev;
    }
}

// Maxpool 2x2 on packed bits == bitwise OR. Words w >= realW are written as 0
// (zero-fills pad groups that the conv no longer computes).
__global__ void pool_kernel(const uint32_t* __restrict__ in, uint32_t* __restrict__ out,
                            int Ho, int Wo, int WORDS, int realW, int total)
{
    int idx = blockIdx.x * blockDim.x + threadIdx.x;
    if (idx >= total) return;
    int w = idx % WORDS; int r = idx / WORDS;
    int xo = r % Wo; r /= Wo;
    int yo = r % Ho; int n = r / Ho;
    if (w >= realW) { out[idx] = 0u; return; }
    const int Wi = Wo * 2;
    size_t base = (((size_t)n * (Ho * 2) + yo * 2) * Wi + xo * 2) * WORDS + w;
    size_t rs = (size_t)Wi * WORDS;
    out[idx] = in[base] | in[base + WORDS] | in[base + rs] | in[base + rs + WORDS];
}

// Binary FC: out[n][o] = 15568 - 2*popc(x ^ w) + fcb[o]
__global__ void fc_kernel(const uint32_t* __restrict__ xb, const uint32_t* __restrict__ wb,
                          const float* __restrict__ fcb, float* __restrict__ out)
{
    int t = blockIdx.x * blockDim.x + threadIdx.x;
    if (t >= NIMG * 10) return;
    int n = t / 10, o = t - n * 10;
    const uint4* xa = (const uint4*)(xb + (size_t)n * 512);
    const uint4* wa = (const uint4*)(wb + (size_t)o * 512);
    int D = 0;
#pragma unroll 8
    for (int i = 0; i < 128; ++i) {
        uint4 a = xa[i], b = wa[i];
        D += __popc(a.x ^ b.x) + __popc(a.y ^ b.y) + __popc(a.z ^ b.z) + __popc(a.w ^ b.w);
    }
    out[t] = (float)(15568 - 2 * D) + fcb[o];
}

// ---------------------------------------------------------------------------
extern "C" void kernel_launch(void* const* d_in, const int* in_sizes, int n_in,
                              void* d_out, int out_size)
{
    static const int s_cin[6]   = {3, 344, 352, 686, 679, 1246};
    static const int s_H[6]     = {32, 32, 16, 16, 8, 8};
    static const int s_winp[6]  = {1, 12, 12, 24, 24, 40};
    static const int s_woutp[6] = {12, 12, 24, 24, 40, 32};   // storage strides
    static const int s_gy[6]    = {12, 11, 24, 22, 40, 31};   // computed groups
    static const size_t s_woff[6] = {0, 3456, 44928, 127872, 293760, 570240};
    static const size_t s_toff[6] = {0, 384, 768, 1536, 2304, 3584};

    const long long szw[6] = {344LL*3*9, 352LL*344*9, 686LL*352*9,
                              679LL*686*9, 1246LL*679*9, 973LL*1246*9};
    const long long szp[6] = {4LL*344, 4LL*352, 4LL*686, 4LL*679, 4LL*1246, 4LL*973};
    auto find = [&](long long s) -> const void* {
        for (int i = 0; i < n_in; ++i)
            if ((long long)in_sizes[i] == s) return d_in[i];
        return (const void*)0;
    };
    const float* x   = (const float*)find(256LL * 3 * 32 * 32);
    const float* fcw = (const float*)find(10LL * 15568);
    const float* fcb = (const float*)find(10);
    const float* w[6]; const float* p[6];
    for (int i = 0; i < 6; ++i) {
        w[i] = (const float*)find(szw[i]);
        p[i] = (const float*)find(szp[i]);
    }
    if (!x || !fcw || !fcb) return;

    void *pA, *pB, *pW, *pPW, *pT, *pF;
    cudaGetSymbolAddress(&pA, g_bufA);
    cudaGetSymbolAddress(&pB, g_bufB);
    cudaGetSymbolAddress(&pW, g_wpk);
    cudaGetSymbolAddress(&pPW, g_wpw);
    cudaGetSymbolAddress(&pT, g_th);
    cudaGetSymbolAddress(&pF, g_fcpk);
    uint32_t* bufA = (uint32_t*)pA;
    uint32_t* bufB = (uint32_t*)pB;
    uint32_t* wpk  = (uint32_t*)pW;
    int*      wpw  = (int*)pPW;
    float2*   th   = (float2*)pT;
    uint32_t* fcpk = (uint32_t*)pF;

    auto smemFor = [](int winp) { return (size_t)(9 * 32 * winp + 288 + 100 * winp) * 4; };
    cudaFuncSetAttribute(bconv_kernel<40>, cudaFuncAttributeMaxDynamicSharedMemorySize, (int)smemFor(40));
    cudaFuncSetAttribute(bconv_kernel<24>, cudaFuncAttributeMaxDynamicSharedMemorySize, (int)smemFor(24));

    // --- pack phase: 2 launches ---
    {
        int tot = NIMG * 1024 + 104320 * 32;
        pack_xw_kernel<<<(tot + 255) / 256, 256>>>(x, w[0], w[1], w[2], w[3], w[4], w[5],
                                                   bufA, wpk);
    }
    {
        int tot = 163840 + 41472 + 4608;
        pack_misc_kernel<<<(tot + 255) / 256, 256>>>(wpk, fcw, p[0], p[1], p[2], p[3], p[4], p[5],
                                                     wpw, th, fcpk);
    }

    // --- conv stack ---
    auto conv = [&](int l, const uint32_t* src, uint32_t* dst) {
        int H = s_H[l], W = H;
        int WINP = s_winp[l], WOUTP = s_woutp[l], Cin = s_cin[l];
        int tilesX = W / 8;
        dim3 grid((unsigned)((H / 8) * tilesX), (unsigned)s_gy[l],
                  (unsigned)(NIMG / IMGS_PER_BLK));
        size_t smem = smemFor(WINP);
        uint8_t* ob = (uint8_t*)dst;
        const uint32_t* wb = wpk + s_woff[l];
        const int* pwb = wpw + s_toff[l] * 9;
        const float2* tb = th + s_toff[l];
        switch (WINP) {
            case 1:  bconv_kernel<1><<<grid, 256, smem>>>(src, ob, wb, pwb, tb, H, W, Cin, WOUTP, tilesX, 1, 2); break;
            case 12: bconv_kernel<12><<<grid, 256, smem>>>(src, ob, wb, pwb, tb, H, W, Cin, WOUTP, tilesX, 1, 2); break;
            case 24: bconv_kernel<24><<<grid, 256, smem>>>(src, ob, wb, pwb, tb, H, W, Cin, WOUTP, tilesX, 1, 2); break;
            case 40: bconv_kernel<40><<<grid, 256, smem>>>(src, ob, wb, pwb, tb, H, W, Cin, WOUTP, tilesX, 1, 2); break;
        }
    };

    conv(0, bufA, bufB);                                    // B: [32,32,12] (word 11 zeroed via thresholds)
    conv(1, bufB, bufA);                                    // A: conv-space [32,32,12], groups 0..10 only
    {   int tot = NIMG * 16 * 16 * 12;
        pool_kernel<<<(tot + 255) / 256, 256>>>(bufA, bufB, 16, 16, 12, 11, tot); }  // B: [16,16,12], word 11 = 0
    conv(2, bufB, bufA);                                    // A: [16,16,24] (words 22,23 zeroed via thresholds)
    conv(3, bufA, bufB);                                    // B: conv-space [16,16,24], groups 0..21 only
    {   int tot = NIMG * 8 * 8 * 24;
        pool_kernel<<<(tot + 255) / 256, 256>>>(bufB, bufA, 8, 8, 24, 22, tot); }    // A: [8,8,24], words 22,23 = 0
    conv(4, bufA, bufB);                                    // B: [8,8,40] (word 39 zeroed via thresholds)
    conv(5, bufB, bufA);                                    // A: conv-space [8,8,32], groups 0..30 only
    {   int tot = NIMG * 4 * 4 * 32;
        pool_kernel<<<(tot + 255) / 256, 256>>>(bufA, bufB, 4, 4, 32, 31, tot); }    // B: [4,4,32], word 31 = 0

    // --- FC ---
    fc_kernel<<<10, 256>>>(bufB, fcpk, fcb, (float*)d_out);
}